// round 1
// baseline (speedup 1.0000x reference)
#include <cuda_runtime.h>
#include <math.h>
#include <stdint.h>

// Problem constants
#define DIMK 4096
#define HQ   32
#define HKV  8
#define HD   128
#define REP  (HQ / HKV)
#define MAXS 4096
#define ATT_SCALE 0.08838834764831845f   // 1/sqrt(128)

// Scratch (device globals: allocation-free per harness rules)
__device__ float g_Q[(size_t)MAXS * HQ * HD];
__device__ float g_K[(size_t)MAXS * HKV * HD];
__device__ float g_V[(size_t)MAXS * HKV * HD];
__device__ float g_O[(size_t)MAXS * HQ * HD];

// ---------------------------------------------------------------------------
// GEMM: C[M,N] = A[M,K] @ B[N,K]^T      (all fp32, M%128==0, N%128==0, K%16==0)
// 128x128 tile, BK=16, 256 threads, 8x8 micro-tile per thread.
// ---------------------------------------------------------------------------
#define GBM 128
#define GBN 128
#define GBK 16

__global__ __launch_bounds__(256, 2)
void gemm_nt(const float* __restrict__ A, const float* __restrict__ B,
             float* __restrict__ C, int M, int N, int K) {
    __shared__ __align__(16) float As[GBK][GBM + 4];
    __shared__ __align__(16) float Bs[GBK][GBN + 4];

    const int tid = threadIdx.x;
    const int rx  = tid & 15;
    const int ry  = tid >> 4;
    const int m0  = ry * 8;
    const int n0  = rx * 8;
    const int bm  = blockIdx.y * GBM;
    const int bn  = blockIdx.x * GBN;

    float acc[8][8];
#pragma unroll
    for (int i = 0; i < 8; i++)
#pragma unroll
        for (int j = 0; j < 8; j++) acc[i][j] = 0.f;

    for (int kb = 0; kb < K; kb += GBK) {
        // Stage A and B tiles (transposed into [k][m] / [k][n])
#pragma unroll
        for (int t = 0; t < 2; t++) {
            int c  = tid + t * 256;        // 512 float4 chunks per tile
            int r  = c >> 2;               // row within tile (0..127)
            int kq = (c & 3) * 4;          // k sub-offset (0,4,8,12)
            float4 a4 = *(const float4*)(A + (size_t)(bm + r) * K + kb + kq);
            As[kq + 0][r] = a4.x;
            As[kq + 1][r] = a4.y;
            As[kq + 2][r] = a4.z;
            As[kq + 3][r] = a4.w;
            float4 b4 = *(const float4*)(B + (size_t)(bn + r) * K + kb + kq);
            Bs[kq + 0][r] = b4.x;
            Bs[kq + 1][r] = b4.y;
            Bs[kq + 2][r] = b4.z;
            Bs[kq + 3][r] = b4.w;
        }
        __syncthreads();

#pragma unroll
        for (int k = 0; k < GBK; k++) {
            float af[8], bf[8];
            *(float4*)&af[0] = *(const float4*)&As[k][m0];
            *(float4*)&af[4] = *(const float4*)&As[k][m0 + 4];
            *(float4*)&bf[0] = *(const float4*)&Bs[k][n0];
            *(float4*)&bf[4] = *(const float4*)&Bs[k][n0 + 4];
#pragma unroll
            for (int i = 0; i < 8; i++)
#pragma unroll
                for (int j = 0; j < 8; j++)
                    acc[i][j] = fmaf(af[i], bf[j], acc[i][j]);
        }
        __syncthreads();
    }

#pragma unroll
    for (int i = 0; i < 8; i++) {
        float* crow = C + (size_t)(bm + m0 + i) * N + bn + n0;
#pragma unroll
        for (int j = 0; j < 8; j += 4) {
            float4 o = make_float4(acc[i][j], acc[i][j + 1], acc[i][j + 2], acc[i][j + 3]);
            *(float4*)(crow + j) = o;
        }
    }
}

// ---------------------------------------------------------------------------
// RoPE (interleaved pairs), in-place on T[S, nh, 128]
// freqs_cis layout: [S, 64, 2] -> fc[s*128 + 2*i + {0:cos,1:sin}]
// ---------------------------------------------------------------------------
__global__ void rope_kernel(float* __restrict__ T, const float* __restrict__ fc,
                            int S, int nh) {
    int idx   = blockIdx.x * blockDim.x + threadIdx.x;
    int total = S * nh * (HD / 2);
    if (idx >= total) return;
    int i = idx & 63;
    int h = (idx >> 6) % nh;
    int s = idx / (64 * nh);
    float c  = fc[(size_t)s * HD + 2 * i];
    float sn = fc[(size_t)s * HD + 2 * i + 1];
    size_t base = ((size_t)s * nh + h) * HD + 2 * i;
    float t0 = T[base];
    float t1 = T[base + 1];
    T[base]     = t0 * c - t1 * sn;
    T[base + 1] = t0 * sn + t1 * c;
}

// ---------------------------------------------------------------------------
// Flash attention with segmented causal mask (GQA via head mapping).
// One block = (64-query tile, head). 128 threads. Online softmax.
// ---------------------------------------------------------------------------
#define QS_STR 129
#define KS_STR 129
#define VS_STR 132
#define SS_STR 65
// floats: Qs 64*129, Ks 64*129, Vs 64*132, Ss 64*65, m/l/alpha 3*64, seg 64 ints
#define ATTN_SMEM_BYTES ((64 * QS_STR + 64 * KS_STR + 64 * VS_STR + 64 * SS_STR + 3 * 64) * 4 + 64 * 4)

__global__ __launch_bounds__(128, 1)
void attn_kernel(const float* __restrict__ Q, const float* __restrict__ K,
                 const float* __restrict__ V, const int* __restrict__ seqlens,
                 int nseq, float* __restrict__ O, int S) {
    extern __shared__ __align__(16) float sm[];
    float* Qs    = sm;
    float* Ks    = Qs + 64 * QS_STR;
    float* Vs    = Ks + 64 * KS_STR;
    float* Ss    = Vs + 64 * VS_STR;
    float* row_m = Ss + 64 * SS_STR;
    float* row_l = row_m + 64;
    float* row_a = row_l + 64;
    int*   seg_s = (int*)(row_a + 64);

    const int tid = threadIdx.x;
    const int h   = blockIdx.y;
    const int kvh = h / REP;
    const int q0  = blockIdx.x * 64;

    // Load Q tile: 64 rows x 128 d (row-major, stride 129)
#pragma unroll
    for (int t = 0; t < 16; t++) {
        int c  = t * 128 + tid;
        int r  = c >> 5;
        int dq = (c & 31) * 4;
        float4 v = *(const float4*)(Q + ((size_t)(q0 + r) * HQ + h) * HD + dq);
        Qs[r * QS_STR + dq + 0] = v.x;
        Qs[r * QS_STR + dq + 1] = v.y;
        Qs[r * QS_STR + dq + 2] = v.z;
        Qs[r * QS_STR + dq + 3] = v.w;
    }
    if (tid < 64) {
        int qg = q0 + tid;
        int cum = 0, ss = 0;
        for (int i = 0; i < nseq; i++) {
            int nc = cum + seqlens[i];
            if (qg < nc) { ss = cum; break; }
            cum = nc;
        }
        seg_s[tid] = ss;
        row_m[tid] = -INFINITY;
        row_l[tid] = 0.f;
    }

    float acc[4][16];
#pragma unroll
    for (int i = 0; i < 4; i++)
#pragma unroll
        for (int j = 0; j < 16; j++) acc[i][j] = 0.f;

    __syncthreads();

    const int kt_lo = seg_s[0] >> 6;   // rows sorted => row 0 has min seg_start
    const int kt_hi = blockIdx.x;
    const int r0  = (tid >> 3) * 4;    // 4 query rows per thread
    const int c0s = (tid & 7) * 8;     // 8 score cols per thread
    const int c0v = (tid & 7) * 16;    // 16 output cols per thread

    for (int kt = kt_lo; kt <= kt_hi; kt++) {
        const int k0 = kt * 64;

        // Load K tile (stride 129) + V tile (row-major, stride 132)
#pragma unroll
        for (int t = 0; t < 16; t++) {
            int c  = t * 128 + tid;
            int r  = c >> 5;
            int dq = (c & 31) * 4;
            size_t gk = ((size_t)(k0 + r) * HKV + kvh) * HD + dq;
            float4 kv = *(const float4*)(K + gk);
            Ks[r * KS_STR + dq + 0] = kv.x;
            Ks[r * KS_STR + dq + 1] = kv.y;
            Ks[r * KS_STR + dq + 2] = kv.z;
            Ks[r * KS_STR + dq + 3] = kv.w;
            float4 vv = *(const float4*)(V + gk);
            *(float4*)&Vs[r * VS_STR + dq] = vv;
        }
        __syncthreads();

        // S = Q @ K^T  (each thread: 4x8 micro-tile)
        float sacc[4][8];
#pragma unroll
        for (int i = 0; i < 4; i++)
#pragma unroll
            for (int j = 0; j < 8; j++) sacc[i][j] = 0.f;

#pragma unroll 4
        for (int d = 0; d < HD; d++) {
            float qf[4], kf[8];
#pragma unroll
            for (int i = 0; i < 4; i++) qf[i] = Qs[(r0 + i) * QS_STR + d];
#pragma unroll
            for (int j = 0; j < 8; j++) kf[j] = Ks[(c0s + j) * KS_STR + d];
#pragma unroll
            for (int i = 0; i < 4; i++)
#pragma unroll
                for (int j = 0; j < 8; j++)
                    sacc[i][j] = fmaf(qf[i], kf[j], sacc[i][j]);
        }
#pragma unroll
        for (int i = 0; i < 4; i++)
#pragma unroll
            for (int j = 0; j < 8; j++)
                Ss[(r0 + i) * SS_STR + c0s + j] = sacc[i][j] * ATT_SCALE;
        __syncthreads();

        // Online softmax (one thread per query row)
        if (tid < 64) {
            int q  = tid;
            int qg = q0 + q;
            int ss = seg_s[q];
            float m_old = row_m[q];
            float m_new = m_old;
            for (int c = 0; c < 64; c++) {
                int kg = k0 + c;
                if (kg >= ss && kg <= qg) {
                    float x = Ss[q * SS_STR + c];
                    if (x > m_new) m_new = x;
                }
            }
            float alpha = (m_new == -INFINITY) ? 1.f : __expf(m_old - m_new);
            float l = row_l[q] * alpha;
            for (int c = 0; c < 64; c++) {
                int kg = k0 + c;
                float p = 0.f;
                if (kg >= ss && kg <= qg)
                    p = __expf(Ss[q * SS_STR + c] - m_new);
                Ss[q * SS_STR + c] = p;
                l += p;
            }
            row_m[q] = m_new;
            row_l[q] = l;
            row_a[q] = alpha;
        }
        __syncthreads();

        // acc = acc*alpha + P @ V  (each thread: 4 rows x 16 cols)
        float al[4];
#pragma unroll
        for (int i = 0; i < 4; i++) al[i] = row_a[r0 + i];
#pragma unroll
        for (int i = 0; i < 4; i++)
#pragma unroll
            for (int j = 0; j < 16; j++) acc[i][j] *= al[i];

#pragma unroll 2
        for (int k = 0; k < 64; k++) {
            float pf[4], vf[16];
#pragma unroll
            for (int i = 0; i < 4; i++) pf[i] = Ss[(r0 + i) * SS_STR + k];
            *(float4*)&vf[0]  = *(const float4*)&Vs[k * VS_STR + c0v];
            *(float4*)&vf[4]  = *(const float4*)&Vs[k * VS_STR + c0v + 4];
            *(float4*)&vf[8]  = *(const float4*)&Vs[k * VS_STR + c0v + 8];
            *(float4*)&vf[12] = *(const float4*)&Vs[k * VS_STR + c0v + 12];
#pragma unroll
            for (int i = 0; i < 4; i++)
#pragma unroll
                for (int j = 0; j < 16; j++)
                    acc[i][j] = fmaf(pf[i], vf[j], acc[i][j]);
        }
        __syncthreads();   // protect Ks/Vs/Ss before next tile
    }

    // Normalize and write O[s, h*128 + d]
#pragma unroll
    for (int i = 0; i < 4; i++) {
        float inv = 1.f / row_l[r0 + i];
        float* orow = O + (size_t)(q0 + r0 + i) * (HQ * HD) + h * HD + c0v;
#pragma unroll
        for (int j = 0; j < 16; j += 4) {
            float4 o = make_float4(acc[i][j] * inv, acc[i][j + 1] * inv,
                                   acc[i][j + 2] * inv, acc[i][j + 3] * inv);
            *(float4*)(orow + j) = o;
        }
    }
}

// ---------------------------------------------------------------------------
// Launch
// Inputs: 0:x[S,4096] 1:freqs_cis[S,64,2] 2:seqlens[int32 x nseq]
//         3:wq[4096,4096] 4:wk[1024,4096] 5:wv[1024,4096] 6:wo[4096,4096]
// Output: float32 [S, 4096]
// ---------------------------------------------------------------------------
extern "C" void kernel_launch(void* const* d_in, const int* in_sizes, int n_in,
                              void* d_out, int out_size) {
    const float* x  = (const float*)d_in[0];
    const float* fc = (const float*)d_in[1];
    const int*   sl = (const int*)d_in[2];
    const float* wq = (const float*)d_in[3];
    const float* wk = (const float*)d_in[4];
    const float* wv = (const float*)d_in[5];
    const float* wo = (const float*)d_in[6];
    float* out = (float*)d_out;

    const int S    = in_sizes[0] / DIMK;   // 2048
    const int nseq = in_sizes[2];

    float *Qp, *Kp, *Vp, *Op;
    cudaGetSymbolAddress((void**)&Qp, g_Q);
    cudaGetSymbolAddress((void**)&Kp, g_K);
    cudaGetSymbolAddress((void**)&Vp, g_V);
    cudaGetSymbolAddress((void**)&Op, g_O);

    // QKV projections
    gemm_nt<<<dim3(HQ * HD / GBN, S / GBM), 256>>>(x, wq, Qp, S, HQ * HD, DIMK);
    gemm_nt<<<dim3(HKV * HD / GBN, S / GBM), 256>>>(x, wk, Kp, S, HKV * HD, DIMK);
    gemm_nt<<<dim3(HKV * HD / GBN, S / GBM), 256>>>(x, wv, Vp, S, HKV * HD, DIMK);

    // RoPE
    {
        int tq = S * HQ * (HD / 2);
        rope_kernel<<<(tq + 255) / 256, 256>>>(Qp, fc, S, HQ);
        int tk = S * HKV * (HD / 2);
        rope_kernel<<<(tk + 255) / 256, 256>>>(Kp, fc, S, HKV);
    }

    // Attention
    cudaFuncSetAttribute(attn_kernel, cudaFuncAttributeMaxDynamicSharedMemorySize,
                         ATTN_SMEM_BYTES);
    attn_kernel<<<dim3(S / 64, HQ), 128, ATTN_SMEM_BYTES>>>(Qp, Kp, Vp, sl, nseq, Op, S);

    // Output projection
    gemm_nt<<<dim3(DIMK / GBN, S / GBM), 256>>>(Op, wo, out, S, DIMK, DIMK);
}